// round 15
// baseline (speedup 1.0000x reference)
#include <cuda_runtime.h>
#include <cuda_fp16.h>
#include <cstddef>

#define Nn   131072
#define Ee   524288
#define Gg   4096
#define DIN  128
#define DH   512
#define DOUT 256
#define BN_EPS 1e-5f

// packed-B segment offsets (uint4 units); k-tile = 64
#define BP_OFF_L1  0
#define BP_OFF_L2  8192
#define BP_OFF_L3  40960
#define BP_OFF_F1  57344
#define BP_OFF_F2  65536
#define BP_TOTAL   73728

// ---------------- scratch ----------------
__device__ float  g_dinv[Nn];
__device__ __half g_h1  [(size_t)Nn * DH];
__device__ __half g_h2  [(size_t)Nn * DH];
__device__ float  g_pool[Gg * DOUT];
__device__ __half g_poolh[Gg * DOUT];
__device__ __half g_tmph [Gg * DOUT];
__device__ uint4  g_bpack[BP_TOTAL];
__device__ int    g_edeg [Nn];
__device__ int    g_offs [Nn + 1];
__device__ int    g_cur  [Nn];
__device__ int    g_eidx [Ee];
__device__ int    g_part [256];

// ---------------- degree ----------------
__global__ void edeg_acc_k(const int* __restrict__ dst, int* edeg) {
    int e = blockIdx.x * blockDim.x + threadIdx.x;
    if (e < Ee) atomicAdd(&edeg[dst[e]], 1);
}

// ---------------- CSR build ----------------
__global__ void scan1_k(const int* __restrict__ in, int* out, int* part) {
    __shared__ int s[512];
    int b = blockIdx.x, t = threadIdx.x;
    int v = in[b * 512 + t];
    s[t] = v; __syncthreads();
    #pragma unroll
    for (int o = 1; o < 512; o <<= 1) {
        int x = (t >= o) ? s[t - o] : 0;
        __syncthreads();
        s[t] += x;
        __syncthreads();
    }
    out[b * 512 + t] = s[t] - v;
    if (t == 511) part[b] = s[t];
}
// merged scan2+scan3 (each block redundantly scans the 256 partials)
__global__ void scan3m_k(int* offs, int* cur, const int* __restrict__ part,
                         const int* __restrict__ edeg, float* dinv) {
    __shared__ int s[256];
    __shared__ int ex[256];
    int t = threadIdx.x;
    int v = part[t];
    s[t] = v; __syncthreads();
    #pragma unroll
    for (int o = 1; o < 256; o <<= 1) {
        int x = (t >= o) ? s[t - o] : 0;
        __syncthreads();
        s[t] += x;
        __syncthreads();
    }
    ex[t] = s[t] - v;
    __syncthreads();
    int i = blockIdx.x * 256 + t;
    int o2 = offs[i] + ex[i >> 9];
    offs[i] = o2;
    cur[i] = o2;
    dinv[i] = rsqrtf(1.0f + (float)edeg[i]);
    if (i == 0) offs[Nn] = Ee;
}
__global__ void fill_k(const int* __restrict__ src, const int* __restrict__ dst,
                       int* cur, int* eidx) {
    int e = blockIdx.x * blockDim.x + threadIdx.x;
    if (e >= Ee) return;
    int d = dst[e];
    int pos = atomicAdd(&cur[d], 1);
    eidx[pos] = src[e];
}

// ---------------- helpers ----------------
__device__ __forceinline__ unsigned f2h2(float a, float b) {
    __half2 h = __floats2half2_rn(a, b);
    return *(unsigned*)&h;
}
__device__ __forceinline__ void u4_to_f8(uint4 u, float* f) {
    float2 a = __half22float2(*(__half2*)&u.x);
    float2 b = __half22float2(*(__half2*)&u.y);
    float2 c = __half22float2(*(__half2*)&u.z);
    float2 d = __half22float2(*(__half2*)&u.w);
    f[0] = a.x; f[1] = a.y; f[2] = b.x; f[3] = b.y;
    f[4] = c.x; f[5] = c.y; f[6] = d.x; f[7] = d.y;
}
__device__ __forceinline__ void mma_f16(float* d, const uint4& a, unsigned b0, unsigned b1) {
    asm volatile(
        "mma.sync.aligned.m16n8k16.row.col.f32.f16.f16.f32 "
        "{%0,%1,%2,%3}, {%4,%5,%6,%7}, {%8,%9}, {%0,%1,%2,%3};"
        : "+f"(d[0]), "+f"(d[1]), "+f"(d[2]), "+f"(d[3])
        : "r"(a.x), "r"(a.y), "r"(a.z), "r"(a.w), "r"(b0), "r"(b1));
}
__device__ __forceinline__ void cp_async16(void* smem, const void* gmem) {
    unsigned s = (unsigned)__cvta_generic_to_shared(smem);
    asm volatile("cp.async.cg.shared.global [%0], [%1], 16;" :: "r"(s), "l"(gmem));
}
__device__ __forceinline__ void red_add_v4(float* addr, float a, float b, float c, float d) {
    asm volatile("red.global.add.v4.f32 [%0], {%1,%2,%3,%4};"
                 :: "l"(addr), "f"(a), "f"(b), "f"(c), "f"(d) : "memory");
}

// ---------------- pack one fp16 B segment (k-tile 64) ----------------
__device__ __forceinline__ void packB_one(const float* __restrict__ W, uint4* __restrict__ out,
                                          int idx, int K, int Nd) {
    int q = idx & 3, grp = (idx >> 2) & 7, ntpl = (idx >> 5) & 7, ks = (idx >> 8) & 3;
    int tile = idx >> 10;
    int nb = Nd >> 7;
    int k0 = (tile / nb) * 64, bxn = tile % nb;
    int n0 = bxn * 128 + ntpl * 16 + grp;
    int kr = k0 + ks * 16 + 2 * q;
    uint4 v;
    v.x = f2h2(W[(size_t)kr * Nd + n0],           W[(size_t)(kr + 1) * Nd + n0]);
    v.y = f2h2(W[(size_t)(kr + 8) * Nd + n0],     W[(size_t)(kr + 9) * Nd + n0]);
    v.z = f2h2(W[(size_t)kr * Nd + n0 + 8],       W[(size_t)(kr + 1) * Nd + n0 + 8]);
    v.w = f2h2(W[(size_t)(kr + 8) * Nd + n0 + 8], W[(size_t)(kr + 9) * Nd + n0 + 8]);
    out[idx] = v;
}
__global__ void packB_all_k(const float* __restrict__ W1, const float* __restrict__ W2,
                            const float* __restrict__ W3, const float* __restrict__ Wf1,
                            const float* __restrict__ Wf2, uint4* __restrict__ out) {
    int idx = blockIdx.x * blockDim.x + threadIdx.x;
    if (idx >= BP_TOTAL) return;
    if (idx < BP_OFF_L2)      packB_one(W1,  out + BP_OFF_L1, idx - BP_OFF_L1, DIN,  DH);
    else if (idx < BP_OFF_L3) packB_one(W2,  out + BP_OFF_L2, idx - BP_OFF_L2, DH,   DH);
    else if (idx < BP_OFF_F1) packB_one(W3,  out + BP_OFF_L3, idx - BP_OFF_L3, DH,   DOUT);
    else if (idx < BP_OFF_F2) packB_one(Wf1, out + BP_OFF_F1, idx - BP_OFF_F1, DOUT, DOUT);
    else                      packB_one(Wf2, out + BP_OFF_F2, idx - BP_OFF_F2, DOUT, DOUT);
}

// ---------------- fp16 tensor GEMM, prepacked B, BK=64, double-buffered ----------------
// EPI: 1 +bias+relu | 2 +bias | 3 scale-by-dinv | 4 +bias+relu+BN    OH: half output
template <int EPI, bool OH>
__global__ __launch_bounds__(256, 2) void hgemm_k(
    const __half* __restrict__ A, const uint4* __restrict__ Bp,
    const float* __restrict__ bias, const float* __restrict__ dinv,
    const float* __restrict__ bg, const float* __restrict__ bbe,
    const float* __restrict__ bm, const float* __restrict__ bv,
    void* __restrict__ Cv,
    int M, int K, int Nd)
{
    extern __shared__ uint4 smemu[];
    uint4* As = smemu;
    uint4* Bs = smemu + 2048;

    const int t    = threadIdx.x;
    const int warp = t >> 5, lane = t & 31;
    const int wm = (warp >> 1) * 32;
    const int wn = (warp & 1) * 64;
    const int grp = lane >> 2, qid = lane & 3;
    const int mt0 = (warp >> 1) * 2, mt1 = mt0 + 1;
    const int nb = Nd >> 7;
    const int T = K >> 6;
    const int bx = blockIdx.x;

    const size_t row0 = (size_t)blockIdx.y * 128;
    const __half* Ablk = A + row0 * K;

    const int fa_ks = t & 3, fa_g = (t >> 2) & 7, fa_mt = t >> 5;
    const __half* ArowLo = Ablk + (size_t)(fa_mt * 16 + fa_g) * K + fa_ks * 16;
    const __half* ArowHi = ArowLo + (size_t)8 * K;
    const int fa_idx = fa_ks * 256 + fa_mt * 32 + fa_g * 4;

    float acc[2][8][4];
    #pragma unroll
    for (int i = 0; i < 2; i++)
        #pragma unroll
        for (int j = 0; j < 8; j++)
            #pragma unroll
            for (int l = 0; l < 4; l++) acc[i][j][l] = 0.f;

    uint4 ra0, ra1, rb0, rb1;
    ra0 = ((const uint4*)ArowLo)[0];
    ra1 = ((const uint4*)ArowLo)[1];
    rb0 = ((const uint4*)ArowHi)[0];
    rb1 = ((const uint4*)ArowHi)[1];

    {
        const uint4* bsrc = Bp + ((size_t)bx) * 1024 + t * 4;
        #pragma unroll
        for (int j = 0; j < 4; j++) cp_async16(&Bs[t * 4 + j], bsrc + j);
        asm volatile("cp.async.commit_group;");
        const unsigned* qa0 = &ra0.x; const unsigned* qa1 = &ra1.x;
        const unsigned* qb0 = &rb0.x; const unsigned* qb1 = &rb1.x;
        #pragma unroll
        for (int q = 0; q < 4; q++)
            As[fa_idx + (q ^ fa_ks)] = make_uint4(qa0[q], qb0[q], qa1[q], qb1[q]);
        asm volatile("cp.async.wait_group 0;");
    }
    __syncthreads();

    for (int i = 0; i < T; i++) {
        const int st = i & 1;
        const bool more = (i + 1 < T);
        if (more) {
            const int kn = (i + 1) * 64;
            ra0 = ((const uint4*)(ArowLo + kn))[0];
            ra1 = ((const uint4*)(ArowLo + kn))[1];
            rb0 = ((const uint4*)(ArowHi + kn))[0];
            rb1 = ((const uint4*)(ArowHi + kn))[1];
            const uint4* bsrc = Bp + ((size_t)(i + 1) * nb + bx) * 1024 + t * 4;
            uint4* bdst = &Bs[(1 - st) * 1024 + t * 4];
            #pragma unroll
            for (int j = 0; j < 4; j++) cp_async16(bdst + j, bsrc + j);
            asm volatile("cp.async.commit_group;");
        }

        const uint4* Ast = &As[st * 1024];
        const uint4* Bst = &Bs[st * 1024];
        #pragma unroll
        for (int ks = 0; ks < 4; ks++) {
            uint4 af0 = Ast[ks * 256 + mt0 * 32 + grp * 4 + (qid ^ ks)];
            uint4 af1 = Ast[ks * 256 + mt1 * 32 + grp * 4 + (qid ^ ks)];
            uint4 bfp[4];
            #pragma unroll
            for (int p = 0; p < 4; p++) {
                int ntpl = (wn >> 4) + p;
                bfp[p] = Bst[ks * 256 + ntpl * 32 + grp * 4 + qid];
            }
            #pragma unroll
            for (int p = 0; p < 4; p++) {
                mma_f16(acc[0][2 * p],     af0, bfp[p].x, bfp[p].y);
                mma_f16(acc[0][2 * p + 1], af0, bfp[p].z, bfp[p].w);
                mma_f16(acc[1][2 * p],     af1, bfp[p].x, bfp[p].y);
                mma_f16(acc[1][2 * p + 1], af1, bfp[p].z, bfp[p].w);
            }
        }

        if (more) {
            uint4* Adst = &As[(1 - st) * 1024];
            const unsigned* qa0 = &ra0.x; const unsigned* qa1 = &ra1.x;
            const unsigned* qb0 = &rb0.x; const unsigned* qb1 = &rb1.x;
            #pragma unroll
            for (int q = 0; q < 4; q++)
                Adst[fa_idx + (q ^ fa_ks)] = make_uint4(qa0[q], qb0[q], qa1[q], qb1[q]);
            asm volatile("cp.async.wait_group 0;");
        }
        __syncthreads();
    }

    // ---- epilogue ----
    #pragma unroll
    for (int mt = 0; mt < 2; mt++) {
        const int gr0 = (int)row0 + wm + mt * 16 + grp;
        float s0 = 1.f, s1 = 1.f;
        if (EPI == 3) { s0 = dinv[gr0]; s1 = dinv[gr0 + 8]; }
        #pragma unroll
        for (int nt = 0; nt < 8; nt++) {
            int gc = bx * 128 + wn + nt * 8 + 2 * qid;
            float2 v0, v1;
            v0.x = acc[mt][nt][0]; v0.y = acc[mt][nt][1];
            v1.x = acc[mt][nt][2]; v1.y = acc[mt][nt][3];
            if (EPI == 3) { v0.x *= s0; v0.y *= s0; v1.x *= s1; v1.y *= s1; }
            if (EPI == 1 || EPI == 2 || EPI == 4) {
                float bx2 = bias[gc], by2 = bias[gc + 1];
                v0.x += bx2; v0.y += by2; v1.x += bx2; v1.y += by2;
                if (EPI == 1) {
                    v0.x = fmaxf(v0.x, 0.f); v0.y = fmaxf(v0.y, 0.f);
                    v1.x = fmaxf(v1.x, 0.f); v1.y = fmaxf(v1.y, 0.f);
                }
                if (EPI == 4) {
                    float scx = bg[gc]     * rsqrtf(bv[gc]     + BN_EPS);
                    float scy = bg[gc + 1] * rsqrtf(bv[gc + 1] + BN_EPS);
                    float mx = bm[gc], my = bm[gc + 1];
                    float ex = bbe[gc], ey = bbe[gc + 1];
                    v0.x = scx * (fmaxf(v0.x, 0.f) - mx) + ex;
                    v0.y = scy * (fmaxf(v0.y, 0.f) - my) + ey;
                    v1.x = scx * (fmaxf(v1.x, 0.f) - mx) + ex;
                    v1.y = scy * (fmaxf(v1.y, 0.f) - my) + ey;
                }
            }
            if (OH) {
                __half* C = (__half*)Cv;
                *(unsigned*)(C + (size_t)gr0 * Nd + gc)       = f2h2(v0.x, v0.y);
                *(unsigned*)(C + (size_t)(gr0 + 8) * Nd + gc) = f2h2(v1.x, v1.y);
            } else {
                float* C = (float*)Cv;
                *(float2*)(C + (size_t)gr0 * Nd + gc)       = v0;
                *(float2*)(C + (size_t)(gr0 + 8) * Nd + gc) = v1;
            }
        }
    }
}

// ---------------- layer-1 input aggregation -> half ----------------
__global__ __launch_bounds__(256) void gather_agg_k(
    const int* __restrict__ offs, const int* __restrict__ eidx,
    const float* __restrict__ x, const float* __restrict__ dinv,
    __half* __restrict__ agg)
{
    int node = blockIdx.x * 8 + (threadIdx.x >> 5);
    int lane = threadIdx.x & 31;
    if (node >= Nn) return;

    float dvn = dinv[node];
    float4 xv = ((const float4*)(x + (size_t)node * DIN))[lane];
    float4 acc;
    acc.x = xv.x * dvn; acc.y = xv.y * dvn; acc.z = xv.z * dvn; acc.w = xv.w * dvn;

    int lo = offs[node], hi = offs[node + 1];
    for (int e = lo; e < hi; e++) {
        int s = eidx[e];
        float ds = dinv[s];
        float4 t = ((const float4*)(x + (size_t)s * DIN))[lane];
        acc.x += t.x * ds; acc.y += t.y * ds; acc.z += t.z * ds; acc.w += t.w * ds;
    }
    uint2 o;
    o.x = f2h2(dvn * acc.x, dvn * acc.y);
    o.y = f2h2(dvn * acc.z, dvn * acc.w);
    ((uint2*)(agg + (size_t)node * DIN))[lane] = o;
}

// ---------------- gather (uint4 lanes: 256 cols/warp) + bias + relu + BN -> half act ----------------
__global__ __launch_bounds__(256) void gather_bn_k(
    const int* __restrict__ offs, const int* __restrict__ eidx,
    const __half* __restrict__ hs, const float* __restrict__ dinv,
    const float* __restrict__ b,
    const float* __restrict__ g, const float* __restrict__ be,
    const float* __restrict__ m, const float* __restrict__ v,
    __half* __restrict__ act, int Nd)
{
    int node = blockIdx.x * 8 + (threadIdx.x >> 5);
    int lane = threadIdx.x & 31;
    if (node >= Nn) return;
    const int q8 = Nd >> 3;                        // uint4 (8 halves) per row
    const int c8 = (blockIdx.y << 5) + lane;       // uint4 index within row

    float acc[8];
    u4_to_f8(((const uint4*)hs)[(size_t)node * q8 + c8], acc);

    int lo = offs[node], hi = offs[node + 1];
    for (int e = lo; e < hi; e++) {
        int s = eidx[e];
        float tf[8];
        u4_to_f8(((const uint4*)hs)[(size_t)s * q8 + c8], tf);
        #pragma unroll
        for (int j = 0; j < 8; j++) acc[j] += tf[j];
    }

    float dv = dinv[node];
    int c = c8 * 8;
    float r[8];
    #pragma unroll
    for (int j = 0; j < 8; j++) {
        float y = fmaxf(dv * acc[j] + b[c + j], 0.f);
        r[j] = g[c + j] * rsqrtf(v[c + j] + BN_EPS) * (y - m[c + j]) + be[c + j];
    }
    uint4 o;
    o.x = f2h2(r[0], r[1]); o.y = f2h2(r[2], r[3]);
    o.z = f2h2(r[4], r[5]); o.w = f2h2(r[6], r[7]);
    ((uint4*)act)[(size_t)node * q8 + c8] = o;
}

// ---------------- layer-3: gather (uint4 lanes) + BN fused into fp32 pooled sums ----------------
__global__ __launch_bounds__(256) void gather_bn_pool_k(
    const int* __restrict__ offs, const int* __restrict__ eidx,
    const __half* __restrict__ hs, const float* __restrict__ dinv,
    const int* __restrict__ batch,
    const float* __restrict__ b,
    const float* __restrict__ g, const float* __restrict__ be,
    const float* __restrict__ m, const float* __restrict__ v,
    float* __restrict__ pooled)
{
    int node = blockIdx.x * 8 + (threadIdx.x >> 5);
    int lane = threadIdx.x & 31;
    if (node >= Nn) return;
    const int q8 = DOUT >> 3;                      // 32 uint4 per row -> 1 slice
    const int c8 = lane;

    float acc[8];
    u4_to_f8(((const uint4*)hs)[(size_t)node * q8 + c8], acc);

    int lo = offs[node], hi = offs[node + 1];
    for (int e = lo; e < hi; e++) {
        int s = eidx[e];
        float tf[8];
        u4_to_f8(((const uint4*)hs)[(size_t)s * q8 + c8], tf);
        #pragma unroll
        for (int j = 0; j < 8; j++) acc[j] += tf[j];
    }

    float dv = dinv[node];
    int c = c8 * 8;
    float r[8];
    #pragma unroll
    for (int j = 0; j < 8; j++) {
        float y = fmaxf(dv * acc[j] + b[c + j], 0.f);
        r[j] = g[c + j] * rsqrtf(v[c + j] + BN_EPS) * (y - m[c + j]) + be[c + j];
    }

    int gph = batch[node];
    float* base = pooled + (size_t)gph * DOUT + c;
    red_add_v4(base,     r[0], r[1], r[2], r[3]);
    red_add_v4(base + 4, r[4], r[5], r[6], r[7]);
}

// ---------------- normalize pooled sums -> mean (half) ----------------
__device__ __forceinline__ int lower_bound_i(const int* a, int n, int key) {
    int lo = 0, hi = n;
    while (lo < hi) { int mid = (lo + hi) >> 1; if (a[mid] < key) lo = mid + 1; else hi = mid; }
    return lo;
}
__global__ void normalize_k(const float* __restrict__ pooled, const int* __restrict__ batch,
                            __half* __restrict__ pooledh)
{
    int gph = blockIdx.x;
    __shared__ int s_lo, s_hi;
    if (threadIdx.x == 0) {
        s_lo = lower_bound_i(batch, Nn, gph);
        s_hi = lower_bound_i(batch, Nn, gph + 1);
    }
    __syncthreads();
    float cnt = (float)((s_hi - s_lo) > 0 ? (s_hi - s_lo) : 1);
    int c = threadIdx.x;
    pooledh[gph * DOUT + c] = __float2half_rn(pooled[gph * DOUT + c] / cnt);
}

// ---------------- launch (single stream, R12 structure) ----------------
extern "C" void kernel_launch(void* const* d_in, const int* in_sizes, int n_in,
                              void* d_out, int out_size)
{
    const float* x   = (const float*)d_in[0];
    const int*   ei  = (const int*)  d_in[1];
    const int*   bat = (const int*)  d_in[2];
    const float* W1  = (const float*)d_in[3];
    const float* b1  = (const float*)d_in[4];
    const float* W2  = (const float*)d_in[5];
    const float* b2  = (const float*)d_in[6];
    const float* W3  = (const float*)d_in[7];
    const float* b3  = (const float*)d_in[8];
    const float* g1  = (const float*)d_in[9];
    const float* be1 = (const float*)d_in[10];
    const float* m1  = (const float*)d_in[11];
    const float* v1  = (const float*)d_in[12];
    const float* g2  = (const float*)d_in[13];
    const float* be2 = (const float*)d_in[14];
    const float* m2  = (const float*)d_in[15];
    const float* v2  = (const float*)d_in[16];
    const float* g3  = (const float*)d_in[17];
    const float* be3 = (const float*)d_in[18];
    const float* m3  = (const float*)d_in[19];
    const float* v3  = (const float*)d_in[20];
    const float* Wf1 = (const float*)d_in[21];
    const float* bf1 = (const float*)d_in[22];
    const float* Wf2 = (const float*)d_in[23];
    const float* bf2 = (const float*)d_in[24];

    const int* src = ei;
    const int* dst = ei + Ee;

    float *p_dinv, *p_pool;
    __half *p_h1, *p_h2, *p_poolh, *p_tmph;
    uint4* p_bp;
    int *p_edeg, *p_offs, *p_cur, *p_eidx, *p_part;
    cudaGetSymbolAddress((void**)&p_dinv, g_dinv);
    cudaGetSymbolAddress((void**)&p_h1,   g_h1);
    cudaGetSymbolAddress((void**)&p_h2,   g_h2);
    cudaGetSymbolAddress((void**)&p_pool, g_pool);
    cudaGetSymbolAddress((void**)&p_poolh,g_poolh);
    cudaGetSymbolAddress((void**)&p_tmph, g_tmph);
    cudaGetSymbolAddress((void**)&p_bp,   g_bpack);
    cudaGetSymbolAddress((void**)&p_edeg, g_edeg);
    cudaGetSymbolAddress((void**)&p_offs, g_offs);
    cudaGetSymbolAddress((void**)&p_cur,  g_cur);
    cudaGetSymbolAddress((void**)&p_eidx, g_eidx);
    cudaGetSymbolAddress((void**)&p_part, g_part);

    const int SMEM = 65536;
    cudaFuncSetAttribute(hgemm_k<1, true>,  cudaFuncAttributeMaxDynamicSharedMemorySize, SMEM);
    cudaFuncSetAttribute(hgemm_k<2, false>, cudaFuncAttributeMaxDynamicSharedMemorySize, SMEM);
    cudaFuncSetAttribute(hgemm_k<3, true>,  cudaFuncAttributeMaxDynamicSharedMemorySize, SMEM);
    cudaFuncSetAttribute(hgemm_k<4, true>,  cudaFuncAttributeMaxDynamicSharedMemorySize, SMEM);

    // zero scratch
    cudaMemsetAsync(p_edeg, 0, Nn * sizeof(int), 0);
    cudaMemsetAsync(p_pool, 0, Gg * DOUT * sizeof(float), 0);

    // pack all weights once (fp16 fragment-major)
    packB_all_k<<<(BP_TOTAL + 255) / 256, 256>>>(W1, W2, W3, Wf1, Wf2, p_bp);

    // degree / dinv / CSR
    edeg_acc_k<<<Ee / 256, 256>>>(dst, p_edeg);
    scan1_k<<<256, 512>>>(p_edeg, p_offs, p_part);
    scan3m_k<<<Nn / 256, 256>>>(p_offs, p_cur, p_part, p_edeg, p_dinv);
    fill_k<<<Ee / 256, 256>>>(src, dst, p_cur, p_eidx);

    // ---- layer 1: aggregate-then-GEMM (Âx)W1 with fused BN epilogue ----
    gather_agg_k<<<Nn / 8, 256>>>(p_offs, p_eidx, x, p_dinv, p_h1);
    hgemm_k<4, true><<<dim3(DH/128, Nn/128), 256, SMEM>>>(p_h1, p_bp + BP_OFF_L1, b1, nullptr, g1, be1, m1, v1, p_h2, Nn, DIN, DH);

    // ---- layer 2: GEMM -> half hs (h1) -> gather -> act (h2) ----
    hgemm_k<3, true><<<dim3(DH/128, Nn/128), 256, SMEM>>>(p_h2, p_bp + BP_OFF_L2, nullptr, p_dinv, nullptr, nullptr, nullptr, nullptr, p_h1, Nn, DH, DH);
    gather_bn_k<<<dim3(Nn / 8, DH / 256), 256>>>(p_offs, p_eidx, p_h1, p_dinv, b2, g2, be2, m2, v2, p_h2, DH);

    // ---- layer 3: GEMM -> half hs (h1) -> gather+BN into pooled sums ----
    hgemm_k<3, true><<<dim3(DOUT/128, Nn/128), 256, SMEM>>>(p_h2, p_bp + BP_OFF_L3, nullptr, p_dinv, nullptr, nullptr, nullptr, nullptr, p_h1, Nn, DH, DOUT);
    gather_bn_pool_k<<<Nn / 8, 256>>>(p_offs, p_eidx, p_h1, p_dinv, bat, b3, g3, be3, m3, v3, p_pool);
    normalize_k<<<Gg, DOUT>>>(p_pool, bat, p_poolh);

    // ---- MLP head ----
    hgemm_k<1, true><<<dim3(DOUT/128, Gg/128), 256, SMEM>>>(p_poolh, p_bp + BP_OFF_F1, bf1, nullptr, nullptr, nullptr, nullptr, nullptr, p_tmph, Gg, DOUT, DOUT);
    hgemm_k<2, false><<<dim3(DOUT/128, Gg/128), 256, SMEM>>>(p_tmph, p_bp + BP_OFF_F2, bf2, nullptr, nullptr, nullptr, nullptr, nullptr, d_out, Gg, DOUT, DOUT);
}

// round 16
// speedup vs baseline: 1.3898x; 1.3898x over previous
#include <cuda_runtime.h>
#include <cuda_fp16.h>
#include <cstddef>

#define Nn   131072
#define Ee   524288
#define Gg   4096
#define DIN  128
#define DH   512
#define DOUT 256
#define BN_EPS 1e-5f

// packed-B segment offsets (uint4 units); k-tile = 64
#define BP_OFF_L1  0
#define BP_OFF_L2  8192
#define BP_OFF_L3  40960
#define BP_OFF_F1  57344
#define BP_OFF_F2  65536
#define BP_TOTAL   73728

// ---------------- scratch ----------------
__device__ float  g_dinv[Nn];
__device__ __half g_h1  [(size_t)Nn * DH];
__device__ __half g_h2  [(size_t)Nn * DH];
__device__ float  g_pool[Gg * DOUT];
__device__ __half g_poolh[Gg * DOUT];
__device__ __half g_tmph [Gg * DOUT];
__device__ uint4  g_bpack[BP_TOTAL];
__device__ int    g_edeg [Nn];
__device__ int    g_offs [Nn + 1];
__device__ int    g_cur  [Nn];
__device__ int    g_eidx [Ee];
__device__ int    g_part [256];

// ---------------- degree ----------------
__global__ void edeg_acc_k(const int* __restrict__ dst, int* edeg) {
    int e = blockIdx.x * blockDim.x + threadIdx.x;
    if (e < Ee) atomicAdd(&edeg[dst[e]], 1);
}

// ---------------- CSR build ----------------
__global__ void scan1_k(const int* __restrict__ in, int* out, int* part) {
    __shared__ int s[512];
    int b = blockIdx.x, t = threadIdx.x;
    int v = in[b * 512 + t];
    s[t] = v; __syncthreads();
    #pragma unroll
    for (int o = 1; o < 512; o <<= 1) {
        int x = (t >= o) ? s[t - o] : 0;
        __syncthreads();
        s[t] += x;
        __syncthreads();
    }
    out[b * 512 + t] = s[t] - v;
    if (t == 511) part[b] = s[t];
}
// merged scan2+scan3 (each block redundantly scans the 256 partials)
__global__ void scan3m_k(int* offs, int* cur, const int* __restrict__ part,
                         const int* __restrict__ edeg, float* dinv) {
    __shared__ int s[256];
    __shared__ int ex[256];
    int t = threadIdx.x;
    int v = part[t];
    s[t] = v; __syncthreads();
    #pragma unroll
    for (int o = 1; o < 256; o <<= 1) {
        int x = (t >= o) ? s[t - o] : 0;
        __syncthreads();
        s[t] += x;
        __syncthreads();
    }
    ex[t] = s[t] - v;
    __syncthreads();
    int i = blockIdx.x * 256 + t;
    int o2 = offs[i] + ex[i >> 9];
    offs[i] = o2;
    cur[i] = o2;
    dinv[i] = rsqrtf(1.0f + (float)edeg[i]);
    if (i == 0) offs[Nn] = Ee;
}
__global__ void fill_k(const int* __restrict__ src, const int* __restrict__ dst,
                       int* cur, int* eidx) {
    int e = blockIdx.x * blockDim.x + threadIdx.x;
    if (e >= Ee) return;
    int d = dst[e];
    int pos = atomicAdd(&cur[d], 1);
    eidx[pos] = src[e];
}

// ---------------- helpers ----------------
__device__ __forceinline__ unsigned f2h2(float a, float b) {
    __half2 h = __floats2half2_rn(a, b);
    return *(unsigned*)&h;
}
__device__ __forceinline__ float4 u2_to_f4(uint2 u) {
    __half2 a = *(__half2*)&u.x;
    __half2 b = *(__half2*)&u.y;
    float2 fa = __half22float2(a);
    float2 fb = __half22float2(b);
    return make_float4(fa.x, fa.y, fb.x, fb.y);
}
__device__ __forceinline__ void mma_f16(float* d, const uint4& a, unsigned b0, unsigned b1) {
    asm volatile(
        "mma.sync.aligned.m16n8k16.row.col.f32.f16.f16.f32 "
        "{%0,%1,%2,%3}, {%4,%5,%6,%7}, {%8,%9}, {%0,%1,%2,%3};"
        : "+f"(d[0]), "+f"(d[1]), "+f"(d[2]), "+f"(d[3])
        : "r"(a.x), "r"(a.y), "r"(a.z), "r"(a.w), "r"(b0), "r"(b1));
}
__device__ __forceinline__ void cp_async16(void* smem, const void* gmem) {
    unsigned s = (unsigned)__cvta_generic_to_shared(smem);
    asm volatile("cp.async.cg.shared.global [%0], [%1], 16;" :: "r"(s), "l"(gmem));
}
__device__ __forceinline__ void red_add_v4(float* addr, float4 v) {
    asm volatile("red.global.add.v4.f32 [%0], {%1,%2,%3,%4};"
                 :: "l"(addr), "f"(v.x), "f"(v.y), "f"(v.z), "f"(v.w) : "memory");
}

// ---------------- pack one fp16 B segment (k-tile 64) ----------------
__device__ __forceinline__ void packB_one(const float* __restrict__ W, uint4* __restrict__ out,
                                          int idx, int K, int Nd) {
    int q = idx & 3, grp = (idx >> 2) & 7, ntpl = (idx >> 5) & 7, ks = (idx >> 8) & 3;
    int tile = idx >> 10;
    int nb = Nd >> 7;
    int k0 = (tile / nb) * 64, bxn = tile % nb;
    int n0 = bxn * 128 + ntpl * 16 + grp;
    int kr = k0 + ks * 16 + 2 * q;
    uint4 v;
    v.x = f2h2(W[(size_t)kr * Nd + n0],           W[(size_t)(kr + 1) * Nd + n0]);
    v.y = f2h2(W[(size_t)(kr + 8) * Nd + n0],     W[(size_t)(kr + 9) * Nd + n0]);
    v.z = f2h2(W[(size_t)kr * Nd + n0 + 8],       W[(size_t)(kr + 1) * Nd + n0 + 8]);
    v.w = f2h2(W[(size_t)(kr + 8) * Nd + n0 + 8], W[(size_t)(kr + 9) * Nd + n0 + 8]);
    out[idx] = v;
}
__global__ void packB_all_k(const float* __restrict__ W1, const float* __restrict__ W2,
                            const float* __restrict__ W3, const float* __restrict__ Wf1,
                            const float* __restrict__ Wf2, uint4* __restrict__ out) {
    int idx = blockIdx.x * blockDim.x + threadIdx.x;
    if (idx >= BP_TOTAL) return;
    if (idx < BP_OFF_L2)      packB_one(W1,  out + BP_OFF_L1, idx - BP_OFF_L1, DIN,  DH);
    else if (idx < BP_OFF_L3) packB_one(W2,  out + BP_OFF_L2, idx - BP_OFF_L2, DH,   DH);
    else if (idx < BP_OFF_F1) packB_one(W3,  out + BP_OFF_L3, idx - BP_OFF_L3, DH,   DOUT);
    else if (idx < BP_OFF_F2) packB_one(Wf1, out + BP_OFF_F1, idx - BP_OFF_F1, DOUT, DOUT);
    else                      packB_one(Wf2, out + BP_OFF_F2, idx - BP_OFF_F2, DOUT, DOUT);
}

// ---------------- fp16 tensor GEMM, prepacked B, BK=64, double-buffered ----------------
// EPI: 1 +bias+relu | 2 +bias | 3 scale-by-dinv | 4 +bias+relu+BN    OH: half output
template <int EPI, bool OH>
__global__ __launch_bounds__(256, 2) void hgemm_k(
    const __half* __restrict__ A, const uint4* __restrict__ Bp,
    const float* __restrict__ bias, const float* __restrict__ dinv,
    const float* __restrict__ bg, const float* __restrict__ bbe,
    const float* __restrict__ bm, const float* __restrict__ bv,
    void* __restrict__ Cv,
    int M, int K, int Nd)
{
    extern __shared__ uint4 smemu[];
    uint4* As = smemu;
    uint4* Bs = smemu + 2048;

    const int t    = threadIdx.x;
    const int warp = t >> 5, lane = t & 31;
    const int wm = (warp >> 1) * 32;
    const int wn = (warp & 1) * 64;
    const int grp = lane >> 2, qid = lane & 3;
    const int mt0 = (warp >> 1) * 2, mt1 = mt0 + 1;
    const int nb = Nd >> 7;
    const int T = K >> 6;
    const int bx = blockIdx.x;

    const size_t row0 = (size_t)blockIdx.y * 128;
    const __half* Ablk = A + row0 * K;

    const int fa_ks = t & 3, fa_g = (t >> 2) & 7, fa_mt = t >> 5;
    const __half* ArowLo = Ablk + (size_t)(fa_mt * 16 + fa_g) * K + fa_ks * 16;
    const __half* ArowHi = ArowLo + (size_t)8 * K;
    const int fa_idx = fa_ks * 256 + fa_mt * 32 + fa_g * 4;

    float acc[2][8][4];
    #pragma unroll
    for (int i = 0; i < 2; i++)
        #pragma unroll
        for (int j = 0; j < 8; j++)
            #pragma unroll
            for (int l = 0; l < 4; l++) acc[i][j][l] = 0.f;

    uint4 ra0, ra1, rb0, rb1;
    ra0 = ((const uint4*)ArowLo)[0];
    ra1 = ((const uint4*)ArowLo)[1];
    rb0 = ((const uint4*)ArowHi)[0];
    rb1 = ((const uint4*)ArowHi)[1];

    {
        const uint4* bsrc = Bp + ((size_t)bx) * 1024 + t * 4;
        #pragma unroll
        for (int j = 0; j < 4; j++) cp_async16(&Bs[t * 4 + j], bsrc + j);
        asm volatile("cp.async.commit_group;");
        const unsigned* qa0 = &ra0.x; const unsigned* qa1 = &ra1.x;
        const unsigned* qb0 = &rb0.x; const unsigned* qb1 = &rb1.x;
        #pragma unroll
        for (int q = 0; q < 4; q++)
            As[fa_idx + (q ^ fa_ks)] = make_uint4(qa0[q], qb0[q], qa1[q], qb1[q]);
        asm volatile("cp.async.wait_group 0;");
    }
    __syncthreads();

    for (int i = 0; i < T; i++) {
        const int st = i & 1;
        const bool more = (i + 1 < T);
        if (more) {
            const int kn = (i + 1) * 64;
            ra0 = ((const uint4*)(ArowLo + kn))[0];
            ra1 = ((const uint4*)(ArowLo + kn))[1];
            rb0 = ((const uint4*)(ArowHi + kn))[0];
            rb1 = ((const uint4*)(ArowHi + kn))[1];
            const uint4* bsrc = Bp + ((size_t)(i + 1) * nb + bx) * 1024 + t * 4;
            uint4* bdst = &Bs[(1 - st) * 1024 + t * 4];
            #pragma unroll
            for (int j = 0; j < 4; j++) cp_async16(bdst + j, bsrc + j);
            asm volatile("cp.async.commit_group;");
        }

        const uint4* Ast = &As[st * 1024];
        const uint4* Bst = &Bs[st * 1024];
        #pragma unroll
        for (int ks = 0; ks < 4; ks++) {
            uint4 af0 = Ast[ks * 256 + mt0 * 32 + grp * 4 + (qid ^ ks)];
            uint4 af1 = Ast[ks * 256 + mt1 * 32 + grp * 4 + (qid ^ ks)];
            uint4 bfp[4];
            #pragma unroll
            for (int p = 0; p < 4; p++) {
                int ntpl = (wn >> 4) + p;
                bfp[p] = Bst[ks * 256 + ntpl * 32 + grp * 4 + qid];
            }
            #pragma unroll
            for (int p = 0; p < 4; p++) {
                mma_f16(acc[0][2 * p],     af0, bfp[p].x, bfp[p].y);
                mma_f16(acc[0][2 * p + 1], af0, bfp[p].z, bfp[p].w);
                mma_f16(acc[1][2 * p],     af1, bfp[p].x, bfp[p].y);
                mma_f16(acc[1][2 * p + 1], af1, bfp[p].z, bfp[p].w);
            }
        }

        if (more) {
            uint4* Adst = &As[(1 - st) * 1024];
            const unsigned* qa0 = &ra0.x; const unsigned* qa1 = &ra1.x;
            const unsigned* qb0 = &rb0.x; const unsigned* qb1 = &rb1.x;
            #pragma unroll
            for (int q = 0; q < 4; q++)
                Adst[fa_idx + (q ^ fa_ks)] = make_uint4(qa0[q], qb0[q], qa1[q], qb1[q]);
            asm volatile("cp.async.wait_group 0;");
        }
        __syncthreads();
    }

    // ---- epilogue ----
    #pragma unroll
    for (int mt = 0; mt < 2; mt++) {
        const int gr0 = (int)row0 + wm + mt * 16 + grp;
        float s0 = 1.f, s1 = 1.f;
        if (EPI == 3) { s0 = dinv[gr0]; s1 = dinv[gr0 + 8]; }
        #pragma unroll
        for (int nt = 0; nt < 8; nt++) {
            int gc = bx * 128 + wn + nt * 8 + 2 * qid;
            float2 v0, v1;
            v0.x = acc[mt][nt][0]; v0.y = acc[mt][nt][1];
            v1.x = acc[mt][nt][2]; v1.y = acc[mt][nt][3];
            if (EPI == 3) { v0.x *= s0; v0.y *= s0; v1.x *= s1; v1.y *= s1; }
            if (EPI == 1 || EPI == 2 || EPI == 4) {
                float bx2 = bias[gc], by2 = bias[gc + 1];
                v0.x += bx2; v0.y += by2; v1.x += bx2; v1.y += by2;
                if (EPI == 1) {
                    v0.x = fmaxf(v0.x, 0.f); v0.y = fmaxf(v0.y, 0.f);
                    v1.x = fmaxf(v1.x, 0.f); v1.y = fmaxf(v1.y, 0.f);
                }
                if (EPI == 4) {
                    float scx = bg[gc]     * rsqrtf(bv[gc]     + BN_EPS);
                    float scy = bg[gc + 1] * rsqrtf(bv[gc + 1] + BN_EPS);
                    float mx = bm[gc], my = bm[gc + 1];
                    float ex = bbe[gc], ey = bbe[gc + 1];
                    v0.x = scx * (fmaxf(v0.x, 0.f) - mx) + ex;
                    v0.y = scy * (fmaxf(v0.y, 0.f) - my) + ey;
                    v1.x = scx * (fmaxf(v1.x, 0.f) - mx) + ex;
                    v1.y = scy * (fmaxf(v1.y, 0.f) - my) + ey;
                }
            }
            if (OH) {
                __half* C = (__half*)Cv;
                *(unsigned*)(C + (size_t)gr0 * Nd + gc)       = f2h2(v0.x, v0.y);
                *(unsigned*)(C + (size_t)(gr0 + 8) * Nd + gc) = f2h2(v1.x, v1.y);
            } else {
                float* C = (float*)Cv;
                *(float2*)(C + (size_t)gr0 * Nd + gc)       = v0;
                *(float2*)(C + (size_t)(gr0 + 8) * Nd + gc) = v1;
            }
        }
    }
}

// ---------------- layer-1 input aggregation -> half ----------------
__global__ __launch_bounds__(256) void gather_agg_k(
    const int* __restrict__ offs, const int* __restrict__ eidx,
    const float* __restrict__ x, const float* __restrict__ dinv,
    __half* __restrict__ agg)
{
    int node = blockIdx.x * 8 + (threadIdx.x >> 5);
    int lane = threadIdx.x & 31;
    if (node >= Nn) return;

    float dvn = dinv[node];
    float4 xv = ((const float4*)(x + (size_t)node * DIN))[lane];
    float4 acc;
    acc.x = xv.x * dvn; acc.y = xv.y * dvn; acc.z = xv.z * dvn; acc.w = xv.w * dvn;

    int lo = offs[node], hi = offs[node + 1];
    for (int e = lo; e < hi; e++) {
        int s = eidx[e];
        float ds = dinv[s];
        float4 t = ((const float4*)(x + (size_t)s * DIN))[lane];
        acc.x += t.x * ds; acc.y += t.y * ds; acc.z += t.z * ds; acc.w += t.w * ds;
    }
    uint2 o;
    o.x = f2h2(dvn * acc.x, dvn * acc.y);
    o.y = f2h2(dvn * acc.z, dvn * acc.w);
    ((uint2*)(agg + (size_t)node * DIN))[lane] = o;
}

// ---------------- column-split gather (uint2 lanes, fp32 accum) + bias + relu + BN -> half act ----------------
__global__ __launch_bounds__(256) void gather_bn_k(
    const int* __restrict__ offs, const int* __restrict__ eidx,
    const __half* __restrict__ hs, const float* __restrict__ dinv,
    const float* __restrict__ b,
    const float* __restrict__ g, const float* __restrict__ be,
    const float* __restrict__ m, const float* __restrict__ v,
    __half* __restrict__ act, int Nd)
{
    int node = blockIdx.x * 8 + (threadIdx.x >> 5);
    int lane = threadIdx.x & 31;
    if (node >= Nn) return;
    const int q = Nd >> 2;                  // uint2 (4 halves) per row
    const int c4 = (blockIdx.y << 5) + lane;

    float4 acc = u2_to_f4(((const uint2*)hs)[(size_t)node * q + c4]);

    int lo = offs[node], hi = offs[node + 1];
    for (int e = lo; e < hi; e++) {
        int s = eidx[e];
        float4 t = u2_to_f4(((const uint2*)hs)[(size_t)s * q + c4]);
        acc.x += t.x; acc.y += t.y; acc.z += t.z; acc.w += t.w;
    }

    float dv = dinv[node];
    int c = c4 * 4;
    float4 bb = *(const float4*)(b + c);
    float4 gg = *(const float4*)(g + c);
    float4 eb = *(const float4*)(be + c);
    float4 mm = *(const float4*)(m + c);
    float4 vv = *(const float4*)(v + c);
    float4 r;
    float y;
    y = fmaxf(dv * acc.x + bb.x, 0.f);
    r.x = gg.x * rsqrtf(vv.x + BN_EPS) * (y - mm.x) + eb.x;
    y = fmaxf(dv * acc.y + bb.y, 0.f);
    r.y = gg.y * rsqrtf(vv.y + BN_EPS) * (y - mm.y) + eb.y;
    y = fmaxf(dv * acc.z + bb.z, 0.f);
    r.z = gg.z * rsqrtf(vv.z + BN_EPS) * (y - mm.z) + eb.z;
    y = fmaxf(dv * acc.w + bb.w, 0.f);
    r.w = gg.w * rsqrtf(vv.w + BN_EPS) * (y - mm.w) + eb.w;

    uint2 o;
    o.x = f2h2(r.x, r.y);
    o.y = f2h2(r.z, r.w);
    ((uint2*)act)[(size_t)node * q + c4] = o;
}

// ---------------- layer-3: gather (uint2 lanes) + BN fused into fp32 pooled sums ----------------
__global__ __launch_bounds__(256) void gather_bn_pool_k(
    const int* __restrict__ offs, const int* __restrict__ eidx,
    const __half* __restrict__ hs, const float* __restrict__ dinv,
    const int* __restrict__ batch,
    const float* __restrict__ b,
    const float* __restrict__ g, const float* __restrict__ be,
    const float* __restrict__ m, const float* __restrict__ v,
    float* __restrict__ pooled)
{
    int node = blockIdx.x * 8 + (threadIdx.x >> 5);
    int lane = threadIdx.x & 31;
    if (node >= Nn) return;
    const int q = DOUT >> 2;
    const int c4 = (blockIdx.y << 5) + lane;

    float4 acc = u2_to_f4(((const uint2*)hs)[(size_t)node * q + c4]);

    int lo = offs[node], hi = offs[node + 1];
    for (int e = lo; e < hi; e++) {
        int s = eidx[e];
        float4 t = u2_to_f4(((const uint2*)hs)[(size_t)s * q + c4]);
        acc.x += t.x; acc.y += t.y; acc.z += t.z; acc.w += t.w;
    }

    float dv = dinv[node];
    int c = c4 * 4;
    float4 bb = *(const float4*)(b + c);
    float4 gg = *(const float4*)(g + c);
    float4 eb = *(const float4*)(be + c);
    float4 mm = *(const float4*)(m + c);
    float4 vv = *(const float4*)(v + c);
    float4 r;
    float y;
    y = fmaxf(dv * acc.x + bb.x, 0.f);
    r.x = gg.x * rsqrtf(vv.x + BN_EPS) * (y - mm.x) + eb.x;
    y = fmaxf(dv * acc.y + bb.y, 0.f);
    r.y = gg.y * rsqrtf(vv.y + BN_EPS) * (y - mm.y) + eb.y;
    y = fmaxf(dv * acc.z + bb.z, 0.f);
    r.z = gg.z * rsqrtf(vv.z + BN_EPS) * (y - mm.z) + eb.z;
    y = fmaxf(dv * acc.w + bb.w, 0.f);
    r.w = gg.w * rsqrtf(vv.w + BN_EPS) * (y - mm.w) + eb.w;

    int gph = batch[node];
    red_add_v4(pooled + (size_t)gph * DOUT + c, r);
}

// ---------------- normalize pooled sums -> mean (half) ----------------
__device__ __forceinline__ int lower_bound_i(const int* a, int n, int key) {
    int lo = 0, hi = n;
    while (lo < hi) { int mid = (lo + hi) >> 1; if (a[mid] < key) lo = mid + 1; else hi = mid; }
    return lo;
}
__global__ void normalize_k(const float* __restrict__ pooled, const int* __restrict__ batch,
                            __half* __restrict__ pooledh)
{
    int gph = blockIdx.x;
    __shared__ int s_lo, s_hi;
    if (threadIdx.x == 0) {
        s_lo = lower_bound_i(batch, Nn, gph);
        s_hi = lower_bound_i(batch, Nn, gph + 1);
    }
    __syncthreads();
    float cnt = (float)((s_hi - s_lo) > 0 ? (s_hi - s_lo) : 1);
    int c = threadIdx.x;
    pooledh[gph * DOUT + c] = __float2half_rn(pooled[gph * DOUT + c] / cnt);
}

// ---------------- launch (single stream, R12 structure) ----------------
extern "C" void kernel_launch(void* const* d_in, const int* in_sizes, int n_in,
                              void* d_out, int out_size)
{
    const float* x   = (const float*)d_in[0];
    const int*   ei  = (const int*)  d_in[1];
    const int*   bat = (const int*)  d_in[2];
    const float* W1  = (const float*)d_in[3];
    const float* b1  = (const float*)d_in[4];
    const float* W2  = (const float*)d_in[5];
    const float* b2  = (const float*)d_in[6];
    const float* W3  = (const float*)d_in[7];
    const float* b3  = (const float*)d_in[8];
    const float* g1  = (const float*)d_in[9];
    const float* be1 = (const float*)d_in[10];
    const float* m1  = (const float*)d_in[11];
    const float* v1  = (const float*)d_in[12];
    const float* g2  = (const float*)d_in[13];
    const float* be2 = (const float*)d_in[14];
    const float* m2  = (const float*)d_in[15];
    const float* v2  = (const float*)d_in[16];
    const float* g3  = (const float*)d_in[17];
    const float* be3 = (const float*)d_in[18];
    const float* m3  = (const float*)d_in[19];
    const float* v3  = (const float*)d_in[20];
    const float* Wf1 = (const float*)d_in[21];
    const float* bf1 = (const float*)d_in[22];
    const float* Wf2 = (const float*)d_in[23];
    const float* bf2 = (const float*)d_in[24];

    const int* src = ei;
    const int* dst = ei + Ee;

    float *p_dinv, *p_pool;
    __half *p_h1, *p_h2, *p_poolh, *p_tmph;
    uint4* p_bp;
    int *p_edeg, *p_offs, *p_cur, *p_eidx, *p_part;
    cudaGetSymbolAddress((void**)&p_dinv, g_dinv);
    cudaGetSymbolAddress((void**)&p_h1,   g_h1);
    cudaGetSymbolAddress((void**)&p_h2,   g_h2);
    cudaGetSymbolAddress((void**)&p_pool, g_pool);
    cudaGetSymbolAddress((void**)&p_poolh,g_poolh);
    cudaGetSymbolAddress((void**)&p_tmph, g_tmph);
    cudaGetSymbolAddress((void**)&p_bp,   g_bpack);
    cudaGetSymbolAddress((void**)&p_edeg, g_edeg);
    cudaGetSymbolAddress((void**)&p_offs, g_offs);
    cudaGetSymbolAddress((void**)&p_cur,  g_cur);
    cudaGetSymbolAddress((void**)&p_eidx, g_eidx);
    cudaGetSymbolAddress((void**)&p_part, g_part);

    const int SMEM = 65536;
    cudaFuncSetAttribute(hgemm_k<1, true>,  cudaFuncAttributeMaxDynamicSharedMemorySize, SMEM);
    cudaFuncSetAttribute(hgemm_k<2, false>, cudaFuncAttributeMaxDynamicSharedMemorySize, SMEM);
    cudaFuncSetAttribute(hgemm_k<3, true>,  cudaFuncAttributeMaxDynamicSharedMemorySize, SMEM);
    cudaFuncSetAttribute(hgemm_k<4, true>,  cudaFuncAttributeMaxDynamicSharedMemorySize, SMEM);

    // zero scratch
    cudaMemsetAsync(p_edeg, 0, Nn * sizeof(int), 0);
    cudaMemsetAsync(p_pool, 0, Gg * DOUT * sizeof(float), 0);

    // pack all weights once (fp16 fragment-major)
    packB_all_k<<<(BP_TOTAL + 255) / 256, 256>>>(W1, W2, W3, Wf1, Wf2, p_bp);

    // degree / dinv / CSR
    edeg_acc_k<<<Ee / 256, 256>>>(dst, p_edeg);
    scan1_k<<<256, 512>>>(p_edeg, p_offs, p_part);
    scan3m_k<<<Nn / 256, 256>>>(p_offs, p_cur, p_part, p_edeg, p_dinv);
    fill_k<<<Ee / 256, 256>>>(src, dst, p_cur, p_eidx);

    // ---- layer 1: aggregate-then-GEMM (Âx)W1 with fused BN epilogue ----
    gather_agg_k<<<Nn / 8, 256>>>(p_offs, p_eidx, x, p_dinv, p_h1);
    hgemm_k<4, true><<<dim3(DH/128, Nn/128), 256, SMEM>>>(p_h1, p_bp + BP_OFF_L1, b1, nullptr, g1, be1, m1, v1, p_h2, Nn, DIN, DH);

    // ---- layer 2: GEMM -> half hs (h1) -> gather -> act (h2) ----
    hgemm_k<3, true><<<dim3(DH/128, Nn/128), 256, SMEM>>>(p_h2, p_bp + BP_OFF_L2, nullptr, p_dinv, nullptr, nullptr, nullptr, nullptr, p_h1, Nn, DH, DH);
    gather_bn_k<<<dim3(Nn / 8, DH / 128), 256>>>(p_offs, p_eidx, p_h1, p_dinv, b2, g2, be2, m2, v2, p_h2, DH);

    // ---- layer 3: GEMM -> half hs (h1) -> gather+BN into pooled sums ----
    hgemm_k<3, true><<<dim3(DOUT/128, Nn/128), 256, SMEM>>>(p_h2, p_bp + BP_OFF_L3, nullptr, p_dinv, nullptr, nullptr, nullptr, nullptr, p_h1, Nn, DH, DOUT);
    gather_bn_pool_k<<<dim3(Nn / 8, DOUT / 128), 256>>>(p_offs, p_eidx, p_h1, p_dinv, bat, b3, g3, be3, m3, v3, p_pool);
    normalize_k<<<Gg, DOUT>>>(p_pool, bat, p_poolh);

    // ---- MLP head ----
    hgemm_k<1, true><<<dim3(DOUT/128, Gg/128), 256, SMEM>>>(p_poolh, p_bp + BP_OFF_F1, bf1, nullptr, nullptr, nullptr, nullptr, nullptr, p_tmph, Gg, DOUT, DOUT);
    hgemm_k<2, false><<<dim3(DOUT/128, Gg/128), 256, SMEM>>>(p_tmph, p_bp + BP_OFF_F2, bf2, nullptr, nullptr, nullptr, nullptr, nullptr, d_out, Gg, DOUT, DOUT);
}